// round 16
// baseline (speedup 1.0000x reference)
#include <cuda_runtime.h>
#include <cstdint>

#define Hs 96
#define Is 100
#define Ts 512
#define Bs 512
#define Gs 288               // 3*H
#define Ms (Ts*Bs)           // 262144 rows
#define NB 7                 // batches per scan cluster
#define TM 64                // proj tile rows
#define NMT (Ms / TM)        // 4096 m-tiles
#define XTILE4 (TM * Is / 4) // 1600 float4 per x tile

// Scratch for input projections: [dir][m][g]
__device__ float g_xproj[2][(size_t)Ms * Gs];

typedef unsigned long long u64;

__device__ __forceinline__ u64 fma2(u64 a, u64 b, u64 c) {
    u64 d;
    asm("fma.rn.f32x2 %0, %1, %2, %3;" : "=l"(d) : "l"(a), "l"(b), "l"(c));
    return d;
}
__device__ __forceinline__ float hsum2(u64 a) {
    float x, y;
    asm("mov.b64 {%0,%1}, %2;" : "=f"(x), "=f"(y) : "l"(a));
    return x + y;
}
__device__ __forceinline__ float sigm(float x) {
    return __fdividef(1.0f, 1.0f + __expf(-x));
}
__device__ __forceinline__ float tanh_(float x) {
    return 1.0f - __fdividef(2.0f, 1.0f + __expf(2.0f * x));
}
__device__ __forceinline__ uint32_t smem_u32(const void* p) {
    uint32_t a;
    asm("{ .reg .u64 t; cvta.to.shared.u64 t, %1; cvt.u32.u64 %0, t; }"
        : "=r"(a) : "l"(p));
    return a;
}
__device__ __forceinline__ void cp_async16(uint32_t dst, const void* src) {
    asm volatile("cp.async.ca.shared.global [%0], [%1], 16;"
                 :: "r"(dst), "l"(src));
}
__device__ __forceinline__ void cp_commit() {
    asm volatile("cp.async.commit_group;");
}
__device__ __forceinline__ void cp_wait0() {
    asm volatile("cp.async.wait_group 0;");
}
__device__ __forceinline__ uint32_t mapa_peer(uint32_t addr, uint32_t prank) {
    uint32_t r;
    asm("mapa.shared::cluster.u32 %0, %1, %2;" : "=r"(r) : "r"(addr), "r"(prank));
    return r;
}
__device__ __forceinline__ void st_cluster_f32(uint32_t addr, float v) {
    asm volatile("st.shared::cluster.f32 [%0], %1;" :: "r"(addr), "f"(v));
}
__device__ __forceinline__ void cluster_sync() {
    asm volatile("barrier.cluster.arrive.aligned;" ::: "memory");
    asm volatile("barrier.cluster.wait.aligned;"   ::: "memory");
}

// ---------------------------------------------------------------------------
// Input projection — persistent, cp.async double-buffered (unchanged R15).
// ---------------------------------------------------------------------------
__global__ __launch_bounds__(256, 2) void proj_kernel(
    const float* __restrict__ x,
    const float* __restrict__ wf, const float* __restrict__ bf,
    const float* __restrict__ wb, const float* __restrict__ bb)
{
    extern __shared__ __align__(16) float psm[];
    float* xs0 = psm;                                  // [TM][100]
    float* xs1 = psm + TM * Is;                        // [TM][100]
    ulonglong2* wq = (ulonglong2*)(psm + 2 * TM * Is); // [25][96]

    const int bx  = blockIdx.x;                        // 0..5
    const int dir = (bx >= 3);
    const int g0  = (dir ? bx - 3 : bx) * 96;
    const int tid = threadIdx.x;

    const float* __restrict__ w    = dir ? wb : wf;
    const float* __restrict__ bias = dir ? bb : bf;

    for (int i = tid; i < 96 * 25; i += 256) {
        const int col = i % 96, k4 = i / 96;
        wq[k4 * 96 + col] = *(const ulonglong2*)(w + (size_t)(g0 + col) * Is + 4 * k4);
    }

    int mt = blockIdx.y;
    {
        const uint32_t dst = smem_u32(xs0);
        const char* src = (const char*)(x + (size_t)mt * TM * Is);
        #pragma unroll
        for (int j = 0; j < 7; j++) {
            const int idx = tid + j * 256;
            if (idx < XTILE4) cp_async16(dst + idx * 16, src + idx * 16);
        }
        cp_commit();
    }

    const int cg = tid & 31;
    const int rg = tid >> 5;

    float bv[3];
    #pragma unroll
    for (int c = 0; c < 3; c++) bv[c] = __ldg(&bias[g0 + cg + 32 * c]);

    cp_wait0();
    __syncthreads();

    int p = 0;
    while (true) {
        const int mtn = mt + gridDim.y;
        const bool has_next = (mtn < NMT);

        float* cur = p ? xs1 : xs0;
        float* nxt = p ? xs0 : xs1;

        if (has_next) {
            const uint32_t dst = smem_u32(nxt);
            const char* src = (const char*)(x + (size_t)mtn * TM * Is);
            #pragma unroll
            for (int j = 0; j < 7; j++) {
                const int idx = tid + j * 256;
                if (idx < XTILE4) cp_async16(dst + idx * 16, src + idx * 16);
            }
            cp_commit();
        }

        u64 acc[8][3];
        #pragma unroll
        for (int r = 0; r < 8; r++)
            #pragma unroll
            for (int c = 0; c < 3; c++) acc[r][c] = 0ull;

        #pragma unroll 5
        for (int k4 = 0; k4 < 25; k4++) {
            ulonglong2 wv[3];
            #pragma unroll
            for (int c = 0; c < 3; c++)
                wv[c] = wq[k4 * 96 + cg + 32 * c];
            #pragma unroll
            for (int r = 0; r < 8; r++) {
                const ulonglong2 xv = *(const ulonglong2*)&cur[(rg * 8 + r) * Is + 4 * k4];
                #pragma unroll
                for (int c = 0; c < 3; c++) {
                    acc[r][c] = fma2(xv.x, wv[c].x, acc[r][c]);
                    acc[r][c] = fma2(xv.y, wv[c].y, acc[r][c]);
                }
            }
        }

        const size_t m0 = (size_t)mt * TM;
        #pragma unroll
        for (int c = 0; c < 3; c++) {
            const int gcol = g0 + cg + 32 * c;
            #pragma unroll
            for (int r = 0; r < 8; r++)
                g_xproj[dir][(m0 + rg * 8 + r) * Gs + gcol] = hsum2(acc[r][c]) + bv[c];
        }

        if (!has_next) break;
        cp_wait0();
        __syncthreads();
        p ^= 1;
        mt = mtn;
    }
}

// ---------------------------------------------------------------------------
// Recurrent scan v3 — 2-CTA CLUSTER split of the hidden dimension.
// 296 CTAs = 148 clusters (74 batch-groups x 2 dirs) x 2 ranks.
// CTA rank r owns h-indices [48r, 48r+48): its 144 threads are the r/z/n gate
// rows for those indices (role = tid/48, i = tid%48, W row = role*96+48r+i,
// W row in 96 registers). Matvec reads the FULL h from own smem (peer's half
// delivered via DSMEM each step). Per SM: 2 CTAs from DIFFERENT clusters ->
// independent sequences overlap each other's epilogue/barrier stalls.
// Step: matvec -> stage2 publish (sigmoids in place) -> __syncthreads ->
// stage3 h-update (write local hsh + peer hsh via st.shared::cluster + out)
// -> barrier.cluster (orders DSMEM stores for peer's next matvec).
// ---------------------------------------------------------------------------
__global__ __launch_bounds__(144, 1) __cluster_dims__(2, 1, 1)
void scan_kernel(
    const float* __restrict__ whf, const float* __restrict__ bhf,
    const float* __restrict__ whb, const float* __restrict__ bhb,
    float* __restrict__ out)
{
    __shared__ __align__(16) float hsh[NB][Hs];    // FULL hidden state
    __shared__ float  rz[NB][Hs];                  // local r [0,48) + z [48,96)
    __shared__ float2 dxn[NB][48];                 // local (dot_n, xp_n)

    const int tid  = threadIdx.x;                  // 0..143
    const int rank = blockIdx.x & 1;
    const int cid  = blockIdx.x >> 1;              // 0..147
    const int dir  = cid & 1;
    const int gi   = cid >> 1;                     // 0..73
    int b0 = 7 * gi; if (b0 > Bs - NB) b0 = Bs - NB;

    const int role = tid / 48;                     // 0 r, 1 z, 2 n
    const int i    = tid - role * 48;              // local h index
    const int hi   = 48 * rank + i;                // global h index
    const int g    = role * Hs + hi;               // W_hh row

    const float* __restrict__ wh = dir ? whb : whf;
    const float* __restrict__ bh = dir ? bhb : bhf;

    // W_hh row -> 96 registers (48 u64)
    u64 w2[48];
    {
        const u64* wrow = (const u64*)(wh + g * Hs);
        #pragma unroll
        for (int j = 0; j < 48; j++) w2[j] = __ldg(&wrow[j]);
    }
    const float bhv = __ldg(&bh[g]);

    for (int k = tid; k < NB * Hs; k += 144) (&hsh[0][0])[k] = 0.0f;

    // Peer address of our h column block (same smem offsets in peer CTA)
    const uint32_t hbase_peer = mapa_peer(smem_u32(&hsh[0][0]), 1 - rank);

    const float* __restrict__ xpb = g_xproj[dir];
    const int t_first = dir ? (Ts - 1) : 0;
    const int tstep   = dir ? -1 : 1;

    float xc[NB], xn[NB];
    #pragma unroll
    for (int bbq = 0; bbq < NB; bbq++)
        xc[bbq] = __ldg(&xpb[((size_t)t_first * Bs + b0 + bbq) * Gs + g]);

    __syncthreads();
    cluster_sync();                                // h zeroed in both CTAs

    int tt = t_first;
    #pragma unroll 1
    for (int t = 0; t < Ts; t++) {
        // Prefetch next step's xp
        const int tn = (t == Ts - 1) ? tt : (tt + tstep);
        #pragma unroll
        for (int bbq = 0; bbq < NB; bbq++)
            xn[bbq] = __ldg(&xpb[((size_t)tn * Bs + b0 + bbq) * Gs + g]);

        // Matvec over FULL h: NB independent fma2 chains, uniform broadcasts
        u64 acc[NB];
        #pragma unroll
        for (int bbq = 0; bbq < NB; bbq++) acc[bbq] = 0ull;
        #pragma unroll
        for (int j = 0; j < 24; j++) {
            ulonglong2 hv[NB];
            #pragma unroll
            for (int bbq = 0; bbq < NB; bbq++)
                hv[bbq] = *(const ulonglong2*)&hsh[bbq][4 * j];
            #pragma unroll
            for (int bbq = 0; bbq < NB; bbq++) {
                acc[bbq] = fma2(w2[2 * j],     hv[bbq].x, acc[bbq]);
                acc[bbq] = fma2(w2[2 * j + 1], hv[bbq].y, acc[bbq]);
            }
        }

        // Stage 2: r/z apply their own sigmoid; n publishes (dot, xp)
        if (role < 2) {
            #pragma unroll
            for (int bbq = 0; bbq < NB; bbq++)
                rz[bbq][role * 48 + i] = sigm(xc[bbq] + hsum2(acc[bbq]) + bhv);
        } else {
            #pragma unroll
            for (int bbq = 0; bbq < NB; bbq++)
                dxn[bbq][i] = make_float2(hsum2(acc[bbq]) + bhv, xc[bbq]);
        }
        __syncthreads();

        // Stage 3: 336 elems over 144 threads (bb = role, role+3, role+6)
        for (int bbq = role; bbq < NB; bbq += 3) {
            const float r = rz[bbq][i];
            const float z = rz[bbq][48 + i];
            const float2 v = dxn[bbq][i];
            const float n = tanh_(fmaf(r, v.x, v.y));
            const float hold = hsh[bbq][hi];
            const float hnew = fmaf(z, hold - n, n);
            hsh[bbq][hi] = hnew;
            st_cluster_f32(hbase_peer + (bbq * Hs + hi) * 4, hnew);
            out[((size_t)tt * Bs + b0 + bbq) * (2 * Hs) + dir * Hs + hi] = hnew;
        }

        // Order DSMEM h-stores for both CTAs' next matvec (release/acquire)
        cluster_sync();

        #pragma unroll
        for (int bbq = 0; bbq < NB; bbq++) xc[bbq] = xn[bbq];
        tt = tn;
    }
}

// ---------------------------------------------------------------------------
extern "C" void kernel_launch(void* const* d_in, const int* in_sizes, int n_in,
                              void* d_out, int out_size)
{
    const float* x      = (const float*)d_in[0];
    const float* w_ih_f = (const float*)d_in[1];
    const float* w_hh_f = (const float*)d_in[2];
    const float* b_ih_f = (const float*)d_in[3];
    const float* b_hh_f = (const float*)d_in[4];
    const float* w_ih_b = (const float*)d_in[5];
    const float* w_hh_b = (const float*)d_in[6];
    const float* b_ih_b = (const float*)d_in[7];
    const float* b_hh_b = (const float*)d_in[8];
    float* out = (float*)d_out;

    const int proj_smem = 2 * TM * Is * sizeof(float) + 25 * 96 * sizeof(ulonglong2);

    static bool attr_done = false;
    if (!attr_done) {
        cudaFuncSetAttribute(proj_kernel,
                             cudaFuncAttributeMaxDynamicSharedMemorySize, proj_smem);
        attr_done = true;
    }

    dim3 pg(6, 49);           // persistent CTAs, 2/SM
    proj_kernel<<<pg, 256, proj_smem>>>(x, w_ih_f, b_ih_f, w_ih_b, b_ih_b);
    scan_kernel<<<296, 144>>>(w_hh_f, b_hh_f, w_hh_b, b_hh_b, out);
}